// round 5
// baseline (speedup 1.0000x reference)
#include <cuda_runtime.h>
#include <cstdint>

// Problem constants
#define B_  8
#define H_  256
#define W_  256
#define P_  8
#define PH_ 32
#define N_  1024   // PH*PH
#define S_  64
#define T_  64
#define INV_TEMP 10.0f
#define LN_EPS 1e-5f

#define STRIP 8                 // horizontally adjacent patches per CTA
#define TILE_BYTES 16384        // one W tile: 64x64 fp32

__device__ __forceinline__ void cp16(uint32_t dst, const void* src) {
    asm volatile("cp.async.cg.shared.global [%0], [%1], 16;\n" :: "r"(dst), "l"(src));
}
__device__ __forceinline__ void cp_commit() {
    asm volatile("cp.async.commit_group;\n" ::: "memory");
}
__device__ __forceinline__ void cp_wait0() {
    asm volatile("cp.async.wait_group 0;\n" ::: "memory");
}

__global__ __launch_bounds__(256)
void scs_kernel(const float* __restrict__ spikes,
                const float* __restrict__ Wd,
                const float* __restrict__ gamma,
                const float* __restrict__ beta,
                const float* __restrict__ gates,
                const float* __restrict__ biases,
                float* __restrict__ out) {
    __shared__ float4 s_w[2][1024];          // double-buffered W tile (2 x 16KB)
    __shared__ float  s_patch[STRIP * 64];   // strip pixels, [patch][64]
    __shared__ float  s_out[2][64];          // double-buffered matvec result

    const int blk = blockIdx.x;              // 0..1023  (8 batches x 128 strips)
    const int b   = blk >> 7;
    const int py  = (blk >> 2) & 31;         // patch row
    const int qx  = blk & 3;                 // strip within row
    const int n0  = (py << 5) + (qx << 3);   // first patch index
    const int tid = threadIdx.x;

    const char* Wbase = (const char*)(Wd + ((size_t)(b * N_ + n0) << 12));
    const uint32_t swb0 = (uint32_t)__cvta_generic_to_shared(&s_w[0][0]);
    const uint32_t swb1 = (uint32_t)__cvta_generic_to_shared(&s_w[1][0]);

    // ---- prefetch tile 0 immediately ----
    {
        uint32_t dst = swb0 + tid * 16;
        const char* src = Wbase + tid * 16;
        cp16(dst,         src);
        cp16(dst + 4096,  src + 4096);
        cp16(dst + 8192,  src + 8192);
        cp16(dst + 12288, src + 12288);
        cp_commit();
    }

    // ---- load strip pixels: 8 rows x 64 contiguous cols = 512 floats ----
    {
        const float* sp = spikes + ((size_t)b << 16) + ((py << 3) * 256) + (qx << 6);
#pragma unroll
        for (int k = 0; k < 2; ++k) {
            const int L = tid + (k << 8);           // 0..511
            const int r = L >> 6, col = L & 63;
            s_patch[((col >> 3) << 6) + (r << 3) + (col & 7)] = sp[r * 256 + col];
        }
    }

    const int jp = tid & 15;     // float4 index within a 64-float row-segment group
    const int r0 = tid >> 4;     // 0..15

#pragma unroll 1
    for (int i = 0; i < STRIP; ++i) {
        cp_wait0();              // tile i resident
        __syncthreads();         // all: tile i ready; buf[(i+1)&1] free; s_out[i&1] free

        // prefetch tile i+1 into the other buffer (streams during compute/epilogue)
        if (i + 1 < STRIP) {
            uint32_t dst = ((i + 1) & 1 ? swb1 : swb0) + tid * 16;
            const char* src = Wbase + (size_t)(i + 1) * TILE_BYTES + tid * 16;
            cp16(dst,         src);
            cp16(dst + 4096,  src + 4096);
            cp16(dst + 8192,  src + 8192);
            cp16(dst + 12288, src + 12288);
            cp_commit();
        }

        // ---- matvec from smem tile ----
        const float4* wb = s_w[i & 1];
        const float4  p  = ((const float4*)(s_patch + (i << 6)))[jp];
        const float4  w0 = wb[tid];
        const float4  w1 = wb[tid + 256];
        const float4  w2 = wb[tid + 512];
        const float4  w3 = wb[tid + 768];

        float a0 = w0.x * p.x + w0.y * p.y + w0.z * p.z + w0.w * p.w;
        float a1 = w1.x * p.x + w1.y * p.y + w1.z * p.z + w1.w * p.w;
        float a2 = w2.x * p.x + w2.y * p.y + w2.z * p.z + w2.w * p.w;
        float a3 = w3.x * p.x + w3.y * p.y + w3.z * p.z + w3.w * p.w;
#pragma unroll
        for (int o = 1; o < 16; o <<= 1) {
            a0 += __shfl_xor_sync(0xffffffffu, a0, o);
            a1 += __shfl_xor_sync(0xffffffffu, a1, o);
            a2 += __shfl_xor_sync(0xffffffffu, a2, o);
            a3 += __shfl_xor_sync(0xffffffffu, a3, o);
        }
        if (jp == 0) {
            float* so = s_out[i & 1];
            so[r0]      = a0;
            so[r0 + 16] = a1;
            so[r0 + 32] = a2;
            so[r0 + 48] = a3;
        }
        __syncthreads();         // s_out[i&1] ready

        // ---- warp 0: LN + softmax(/0.1) + gated affine + direct fold-store ----
        if (tid < 32) {
            const float* so = s_out[i & 1];
            const float* sq_ = s_patch + (i << 6);
            const float v0 = so[tid];
            const float v1 = so[tid + 32];
            const float q0 = sq_[tid];
            const float q1 = sq_[tid + 32];

            float ps = q0 + q1;
            float sm = v0 + v1;
#pragma unroll
            for (int o = 16; o > 0; o >>= 1) {
                ps += __shfl_xor_sync(0xffffffffu, ps, o);
                sm += __shfl_xor_sync(0xffffffffu, sm, o);
            }
            const float mu = sm * (1.0f / 64.0f);
            const float d0 = v0 - mu, d1 = v1 - mu;
            float sq = d0 * d0 + d1 * d1;
#pragma unroll
            for (int o = 16; o > 0; o >>= 1)
                sq += __shfl_xor_sync(0xffffffffu, sq, o);
            const float rstd = rsqrtf(sq * (1.0f / 64.0f) + LN_EPS);

            const float z0 = (d0 * rstd * __ldg(&gamma[tid])      + __ldg(&beta[tid]))      * INV_TEMP;
            const float z1 = (d1 * rstd * __ldg(&gamma[tid + 32]) + __ldg(&beta[tid + 32])) * INV_TEMP;

            float mx = fmaxf(z0, z1);
#pragma unroll
            for (int o = 16; o > 0; o >>= 1)
                mx = fmaxf(mx, __shfl_xor_sync(0xffffffffu, mx, o));

            const float e0 = __expf(z0 - mx);
            const float e1 = __expf(z1 - mx);
            float se = e0 + e1;
#pragma unroll
            for (int o = 16; o > 0; o >>= 1)
                se += __shfl_xor_sync(0xffffffffu, se, o);

            const int   n      = n0 + i;
            const float affine = __ldg(&gates[n]) * ps + __ldg(&biases[n]);
            const float scale  = affine / se;

            // fold: pixel t -> (py*8 + t/8, (qx*8+i)*8 + t%8)
            const size_t ob = ((size_t)b << 16) + (((qx << 3) + i) << 3);
            out[ob + ((py << 3) + (tid >> 3)) * 256 + (tid & 7)] = e0 * scale;
            const int t2 = tid + 32;
            out[ob + ((py << 3) + (t2 >> 3)) * 256 + (t2 & 7)]   = e1 * scale;
        }
    }
}

extern "C" void kernel_launch(void* const* d_in, const int* in_sizes, int n_in,
                              void* d_out, int out_size) {
    const float* spikes = (const float*)d_in[0];
    const float* Wd     = (const float*)d_in[1];
    const float* gamma  = (const float*)d_in[2];
    const float* beta   = (const float*)d_in[3];
    const float* gates  = (const float*)d_in[4];
    const float* biases = (const float*)d_in[5];
    float* out = (float*)d_out;

    scs_kernel<<<(B_ * N_) / STRIP, 256>>>(spikes, Wd, gamma, beta, gates, biases, out);
}

// round 6
// speedup vs baseline: 1.0589x; 1.0589x over previous
#include <cuda_runtime.h>
#include <cstdint>

// Problem constants
#define B_  8
#define N_  1024
#define NTOT 8192            // B_*N_ total patch tiles
#define INV_TEMP 10.0f
#define LN_EPS 1e-5f
#define TILE_BYTES 16384     // one W tile: 64x64 fp32

#define GRID 592             // 148 SMs x 4 CTAs -> exactly one wave
// 8192 = 496*14 + 96*13
#define BIG_CTAS 496

// ---- mbarrier / bulk-copy helpers ----
__device__ __forceinline__ void mbar_init(uint32_t mbar, uint32_t count) {
    asm volatile("mbarrier.init.shared.b64 [%0], %1;" :: "r"(mbar), "r"(count) : "memory");
}
__device__ __forceinline__ void mbar_expect_tx(uint32_t mbar, uint32_t bytes) {
    asm volatile("mbarrier.arrive.expect_tx.shared.b64 _, [%0], %1;" :: "r"(mbar), "r"(bytes) : "memory");
}
__device__ __forceinline__ void tma_bulk(uint32_t dst, const void* src, uint32_t bytes, uint32_t mbar) {
    asm volatile("cp.async.bulk.shared::cta.global.mbarrier::complete_tx::bytes [%0], [%1], %2, [%3];"
                 :: "r"(dst), "l"(src), "r"(bytes), "r"(mbar) : "memory");
}
__device__ __forceinline__ void mbar_wait(uint32_t mbar, uint32_t parity) {
    uint32_t done;
    asm volatile(
        "{\n\t.reg .pred p;\n\t"
        "mbarrier.try_wait.parity.acquire.cta.shared::cta.b64 p, [%1], %2;\n\t"
        "selp.b32 %0, 1, 0, p;\n\t}"
        : "=r"(done) : "r"(mbar), "r"(parity) : "memory");
    if (!done) {
        asm volatile(
            "{\n\t.reg .pred P1;\n\t"
            "WAIT_LOOP_%=:\n\t"
            "mbarrier.try_wait.parity.acquire.cta.shared::cta.b64 P1, [%0], %1, 0x989680;\n\t"
            "@P1 bra.uni WAIT_DONE_%=;\n\t"
            "bra.uni WAIT_LOOP_%=;\n\t"
            "WAIT_DONE_%=:\n\t}"
            :: "r"(mbar), "r"(parity) : "memory");
    }
}

__global__ __launch_bounds__(256, 4)
void scs_kernel(const float* __restrict__ spikes,
                const float* __restrict__ Wd,
                const float* __restrict__ gamma,
                const float* __restrict__ beta,
                const float* __restrict__ gates,
                const float* __restrict__ biases,
                float* __restrict__ out) {
    __shared__ __align__(128) float4 s_w[2][1024];   // depth-2 W tile ring (2 x 16KB)
    __shared__ float s_patch[2][64];                  // pixel double buffer
    __shared__ float s_out[64];
    __shared__ __align__(8) unsigned long long s_mbar[2];

    const int tid = threadIdx.x;
    const int cta = blockIdx.x;

    int start, cnt;
    if (cta < BIG_CTAS) { start = cta * 14;                       cnt = 14; }
    else                { start = BIG_CTAS * 14 + (cta - BIG_CTAS) * 13; cnt = 13; }

    const uint32_t mb0 = (uint32_t)__cvta_generic_to_shared(&s_mbar[0]);
    const uint32_t mb1 = mb0 + 8;
    const uint32_t sw0 = (uint32_t)__cvta_generic_to_shared(&s_w[0][0]);

    if (tid == 0) { mbar_init(mb0, 1); mbar_init(mb1, 1); }
    __syncthreads();

    // prologue: prefetch tiles 0,1 via bulk-async; load patch0 pixels
    if (tid == 0) {
        mbar_expect_tx(mb0, TILE_BYTES);
        tma_bulk(sw0, (const char*)Wd + (size_t)start * TILE_BYTES, TILE_BYTES, mb0);
        if (cnt > 1) {
            mbar_expect_tx(mb1, TILE_BYTES);
            tma_bulk(sw0 + TILE_BYTES, (const char*)Wd + (size_t)(start + 1) * TILE_BYTES,
                     TILE_BYTES, mb1);
        }
    }
    if (tid < 64) {
        const int g = start, b = g >> 10, n = g & 1023;
        s_patch[0][tid] = spikes[((size_t)b << 16) + (((n >> 5) << 3) + (tid >> 3)) * 256
                                 + ((n & 31) << 3) + (tid & 7)];
    }
    __syncthreads();

    const int jp = tid & 15;
    const int r0 = tid >> 4;

#pragma unroll 1
    for (int i = 0; i < cnt; ++i) {
        const int sl = i & 1;
        mbar_wait(sl ? mb1 : mb0, (i >> 1) & 1);

        // ---- matvec from smem tile ----
        const float4* wb = s_w[sl];
        const float4  p  = ((const float4*)s_patch[sl])[jp];
        const float4  w0 = wb[tid];
        const float4  w1 = wb[tid + 256];
        const float4  w2 = wb[tid + 512];
        const float4  w3 = wb[tid + 768];

        float a0 = w0.x * p.x + w0.y * p.y + w0.z * p.z + w0.w * p.w;
        float a1 = w1.x * p.x + w1.y * p.y + w1.z * p.z + w1.w * p.w;
        float a2 = w2.x * p.x + w2.y * p.y + w2.z * p.z + w2.w * p.w;
        float a3 = w3.x * p.x + w3.y * p.y + w3.z * p.z + w3.w * p.w;
#pragma unroll
        for (int o = 1; o < 16; o <<= 1) {
            a0 += __shfl_xor_sync(0xffffffffu, a0, o);
            a1 += __shfl_xor_sync(0xffffffffu, a1, o);
            a2 += __shfl_xor_sync(0xffffffffu, a2, o);
            a3 += __shfl_xor_sync(0xffffffffu, a3, o);
        }
        if (jp == 0) {
            s_out[r0]      = a0;
            s_out[r0 + 16] = a1;
            s_out[r0 + 32] = a2;
            s_out[r0 + 48] = a3;
        }
        __syncthreads();   // tile slot free; s_out ready

        // refill the just-freed slot with tile i+2 (streams during epilogue/next matvec)
        if (tid == 0 && i + 2 < cnt) {
            const uint32_t mb = sl ? mb1 : mb0;
            mbar_expect_tx(mb, TILE_BYTES);
            tma_bulk(sw0 + (uint32_t)sl * TILE_BYTES,
                     (const char*)Wd + (size_t)(start + i + 2) * TILE_BYTES, TILE_BYTES, mb);
        }
        // prefetch next patch pixels into the other pixel buffer
        if (tid < 64 && i + 1 < cnt) {
            const int g = start + i + 1, b = g >> 10, n = g & 1023;
            s_patch[sl ^ 1][tid] = spikes[((size_t)b << 16)
                                          + (((n >> 5) << 3) + (tid >> 3)) * 256
                                          + ((n & 31) << 3) + (tid & 7)];
        }

        // ---- warp 0: LN + softmax(/0.1) + gated affine + fold store ----
        if (tid < 32) {
            const int   g  = start + i;
            const int   b  = g >> 10, n = g & 1023;
            const float v0 = s_out[tid];
            const float v1 = s_out[tid + 32];
            const float q0 = s_patch[sl][tid];
            const float q1 = s_patch[sl][tid + 32];

            float ps = q0 + q1;
            float sm = v0 + v1;
            float s2 = v0 * v0 + v1 * v1;
#pragma unroll
            for (int o = 16; o > 0; o >>= 1) {
                ps += __shfl_xor_sync(0xffffffffu, ps, o);
                sm += __shfl_xor_sync(0xffffffffu, sm, o);
                s2 += __shfl_xor_sync(0xffffffffu, s2, o);
            }
            const float mu   = sm * (1.0f / 64.0f);
            const float var  = s2 * (1.0f / 64.0f) - mu * mu;
            const float rstd = rsqrtf(var + LN_EPS);

            const float z0 = ((v0 - mu) * rstd * __ldg(&gamma[tid])      + __ldg(&beta[tid]))      * INV_TEMP;
            const float z1 = ((v1 - mu) * rstd * __ldg(&gamma[tid + 32]) + __ldg(&beta[tid + 32])) * INV_TEMP;

            float mx = fmaxf(z0, z1);
#pragma unroll
            for (int o = 16; o > 0; o >>= 1)
                mx = fmaxf(mx, __shfl_xor_sync(0xffffffffu, mx, o));

            const float e0 = __expf(z0 - mx);
            const float e1 = __expf(z1 - mx);
            float se = e0 + e1;
#pragma unroll
            for (int o = 16; o > 0; o >>= 1)
                se += __shfl_xor_sync(0xffffffffu, se, o);

            const float affine = __ldg(&gates[n]) * ps + __ldg(&biases[n]);
            const float scale  = affine / se;

            const int py = n >> 5, px = n & 31;
            const size_t ob = ((size_t)b << 16) + (px << 3);
            out[ob + ((py << 3) + (tid >> 3)) * 256 + (tid & 7)] = e0 * scale;
            const int t2 = tid + 32;
            out[ob + ((py << 3) + (t2 >> 3)) * 256 + (t2 & 7)]   = e1 * scale;
        }
        __syncthreads();   // pixel buffer + s_out consumed before next iter
    }
}

extern "C" void kernel_launch(void* const* d_in, const int* in_sizes, int n_in,
                              void* d_out, int out_size) {
    const float* spikes = (const float*)d_in[0];
    const float* Wd     = (const float*)d_in[1];
    const float* gamma  = (const float*)d_in[2];
    const float* beta   = (const float*)d_in[3];
    const float* gates  = (const float*)d_in[4];
    const float* biases = (const float*)d_in[5];
    float* out = (float*)d_out;

    scs_kernel<<<GRID, 256>>>(spikes, Wd, gamma, beta, gates, biases, out);
}

// round 7
// speedup vs baseline: 1.2159x; 1.1483x over previous
#include <cuda_runtime.h>
#include <cstdint>

// Problem constants
#define B_  8
#define N_  1024
#define NTOT 8192
#define INV_TEMP 10.0f
#define LN_EPS 1e-5f

// 2 MB scratch for raw matvec results [NTOT][64]
__device__ float g_raw[NTOT * 64];

// ============ Kernel 1: pure streaming matvec (no smem, no barriers) ============
__global__ __launch_bounds__(256)
void scs_matvec(const float* __restrict__ spikes,
                const float* __restrict__ Wd) {
    const int blk = blockIdx.x;          // patch tile g = b*1024 + n
    const int tid = threadIdx.x;
    const int b   = blk >> 10;
    const int n   = blk & 1023;
    const int py  = n >> 5;
    const int px  = n & 31;

    // ---- per-warp direct patch load: lane (tid&15) gets patch float4 jp ----
    const int jp = tid & 15;             // float4 index within the 64-pixel patch
    const float4* sp = (const float4*)(spikes + ((size_t)b << 16)
                                       + ((py << 3) + (jp >> 1)) * 256
                                       + (px << 3) + ((jp & 1) << 2));
    const float4 p = __ldg(sp);

    // ---- warp-contiguous streaming W loads (512B per warp instruction) ----
    const float4* Wp = (const float4*)(Wd + ((size_t)blk << 12));
    const float4 w0 = __ldcs(Wp + tid);
    const float4 w1 = __ldcs(Wp + tid + 256);
    const float4 w2 = __ldcs(Wp + tid + 512);
    const float4 w3 = __ldcs(Wp + tid + 768);

    float a0 = w0.x * p.x + w0.y * p.y + w0.z * p.z + w0.w * p.w;
    float a1 = w1.x * p.x + w1.y * p.y + w1.z * p.z + w1.w * p.w;
    float a2 = w2.x * p.x + w2.y * p.y + w2.z * p.z + w2.w * p.w;
    float a3 = w3.x * p.x + w3.y * p.y + w3.z * p.z + w3.w * p.w;

    // reduce over the 16 lanes sharing a row (bit4 of lane preserved)
#pragma unroll
    for (int o = 1; o < 16; o <<= 1) {
        a0 += __shfl_xor_sync(0xffffffffu, a0, o);
        a1 += __shfl_xor_sync(0xffffffffu, a1, o);
        a2 += __shfl_xor_sync(0xffffffffu, a2, o);
        a3 += __shfl_xor_sync(0xffffffffu, a3, o);
    }
    if (jp == 0) {
        const int r0 = tid >> 4;         // 0..15
        float* dst = g_raw + ((size_t)blk << 6);
        dst[r0]      = a0;
        dst[r0 + 16] = a1;
        dst[r0 + 32] = a2;
        dst[r0 + 48] = a3;
    }
}

// ============ Kernel 2: LN + softmax + gated affine + fold (1 warp / patch) ============
__global__ __launch_bounds__(256)
void scs_epilogue(const float* __restrict__ spikes,
                  const float* __restrict__ gamma,
                  const float* __restrict__ beta,
                  const float* __restrict__ gates,
                  const float* __restrict__ biases,
                  float* __restrict__ out) {
    const int w   = threadIdx.x >> 5;            // warp in CTA (0..7)
    const int l   = threadIdx.x & 31;
    const int g   = (blockIdx.x << 3) + w;       // patch tile index
    const int b   = g >> 10;
    const int n   = g & 1023;
    const int py  = n >> 5;
    const int px  = n & 31;

    const float* raw = g_raw + ((size_t)g << 6);
    const float v0 = raw[l];
    const float v1 = raw[l + 32];

    // patch pixels l and l+32 (for the spike-mass sum)
    const float* sb = spikes + ((size_t)b << 16) + (py << 3) * 256 + (px << 3);
    const float q0 = __ldg(&sb[(l >> 3) * 256 + (l & 7)]);
    const int l2 = l + 32;
    const float q1 = __ldg(&sb[(l2 >> 3) * 256 + (l2 & 7)]);

    float ps = q0 + q1;
    float sm = v0 + v1;
    float s2 = v0 * v0 + v1 * v1;
#pragma unroll
    for (int o = 16; o > 0; o >>= 1) {
        ps += __shfl_xor_sync(0xffffffffu, ps, o);
        sm += __shfl_xor_sync(0xffffffffu, sm, o);
        s2 += __shfl_xor_sync(0xffffffffu, s2, o);
    }
    const float mu   = sm * (1.0f / 64.0f);
    const float var  = s2 * (1.0f / 64.0f) - mu * mu;
    const float rstd = rsqrtf(var + LN_EPS);

    const float z0 = ((v0 - mu) * rstd * __ldg(&gamma[l])  + __ldg(&beta[l]))  * INV_TEMP;
    const float z1 = ((v1 - mu) * rstd * __ldg(&gamma[l2]) + __ldg(&beta[l2])) * INV_TEMP;

    float mx = fmaxf(z0, z1);
#pragma unroll
    for (int o = 16; o > 0; o >>= 1)
        mx = fmaxf(mx, __shfl_xor_sync(0xffffffffu, mx, o));

    const float e0 = __expf(z0 - mx);
    const float e1 = __expf(z1 - mx);
    float se = e0 + e1;
#pragma unroll
    for (int o = 16; o > 0; o >>= 1)
        se += __shfl_xor_sync(0xffffffffu, se, o);

    const float affine = __ldg(&gates[n]) * ps + __ldg(&biases[n]);
    const float scale  = affine / se;

    float* ob = out + ((size_t)b << 16) + (py << 3) * 256 + (px << 3);
    ob[(l >> 3) * 256 + (l & 7)]   = e0 * scale;
    ob[(l2 >> 3) * 256 + (l2 & 7)] = e1 * scale;
}

extern "C" void kernel_launch(void* const* d_in, const int* in_sizes, int n_in,
                              void* d_out, int out_size) {
    const float* spikes = (const float*)d_in[0];
    const float* Wd     = (const float*)d_in[1];
    const float* gamma  = (const float*)d_in[2];
    const float* beta   = (const float*)d_in[3];
    const float* gates  = (const float*)d_in[4];
    const float* biases = (const float*)d_in[5];
    float* out = (float*)d_out;

    scs_matvec<<<NTOT, 256>>>(spikes, Wd);
    scs_epilogue<<<NTOT / 8, 256>>>(spikes, gamma, beta, gates, biases, out);
}